// round 13
// baseline (speedup 1.0000x reference)
#include <cuda_runtime.h>
#include <stdint.h>

#define OUTF 8192
#define INF  8192
#define GROUPS 256            // groups of 32 in-features (3 packed words each)
#define KS 32                 // split-K factor
#define GPB (GROUPS / KS)     // 8 groups per block
#define TPB 128
#define COLS_PER_THREAD 2
#define COLS_PER_BLOCK (TPB * COLS_PER_THREAD)   // 256
#define NCB (OUTF / COLS_PER_BLOCK)              // 32
#define ROWSTRIDE2 (OUTF / 2)                    // uint2 row stride
#define SLOTS 34                                  // 17 packed x pairs per group

// split-K partial dot products: partial[k][n] = sum over K-slice k of x*q
__device__ float g_partial[KS * OUTF];
// per-stripe completion counters (zero-init; reducer resets to 0 each launch)
__device__ int g_count[NCB];

// One extraction pair, shift-free:
//   lo = (a & AM) | 0x4B000000  -> 2^23 + v_lo * 2^b_lo   (in-place field)
//   hi = (b & BM) | 0x4B000000  -> 2^23 + v_hi * 2^b_hi
// x slots are pre-scaled by 2^-b at staging (exact), so after one packed
// de-bias (ADD2) a single FFMA2 accumulates both exact products.
template <unsigned AM, unsigned BM>
__device__ __forceinline__ void dqpm(unsigned a, unsigned b, unsigned long long xp,
                                     unsigned long long nb, unsigned long long &acc) {
    unsigned lo, hi;
    asm("lop3.b32 %0, %1, %2, 0x4B000000, 0xEA;" : "=r"(lo) : "r"(a), "n"(AM));
    asm("lop3.b32 %0, %1, %2, 0x4B000000, 0xEA;" : "=r"(hi) : "r"(b), "n"(BM));
    unsigned long long f;
    asm("mov.b64 %0, {%1, %2};" : "=l"(f) : "r"(lo), "r"(hi));
    asm("add.rn.f32x2 %0, %1, %2;" : "=l"(f) : "l"(f), "l"(nb));
    asm("fma.rn.f32x2 %0, %1, %2, %3;" : "=l"(acc) : "l"(xp), "l"(f), "l"(acc));
}

// first half of a group: 9 pairs (w0's five, w1's first four)
__device__ __forceinline__ void unpack_h1(unsigned w0, unsigned w1,
                                          unsigned s0, unsigned s1,
                                          const unsigned long long* __restrict__ xpr,
                                          unsigned long long nb,
                                          unsigned long long &accA, unsigned long long &accB) {
    dqpm<(0x7u),      (0x7u << 3)> (w0, w0, xpr[0], nb, accA);
    dqpm<(0x7u << 6), (0x7u << 9)> (w0, w0, xpr[1], nb, accB);
    dqpm<(0x7u << 12),(0x7u << 15)>(w0, w0, xpr[2], nb, accA);
    dqpm<(0x7u << 18),(0x7u << 5)> (w0, s0, xpr[3], nb, accB);
    dqpm<(0x7u << 8), (0x7u << 11)>(s0, s0, xpr[4], nb, accA);
    dqpm<(0x7u << 1), (0x7u << 4)> (w1, w1, xpr[5], nb, accB);
    dqpm<(0x7u << 7), (0x7u << 10)>(w1, w1, xpr[6], nb, accA);
    dqpm<(0x7u << 13),(0x7u << 16)>(w1, w1, xpr[7], nb, accB);
    dqpm<(0x7u << 19),(0x7u << 6)> (w1, s1, xpr[8], nb, accA);
}

// second half: remaining 8 pairs (w1 tail, w2's five, two boundary pairs)
__device__ __forceinline__ void unpack_h2(unsigned w1, unsigned w2,
                                          unsigned s0, unsigned s1, unsigned s2,
                                          const unsigned long long* __restrict__ xpr,
                                          unsigned long long nb,
                                          unsigned long long &accA, unsigned long long &accB) {
    dqpm<(0x7u << 9), (0x7u << 12)>(s1, s1, xpr[0], nb, accB);
    dqpm<(0x7u << 2), (0x7u << 5)> (w2, w2, xpr[1], nb, accA);
    dqpm<(0x7u << 8), (0x7u << 11)>(w2, w2, xpr[2], nb, accB);
    dqpm<(0x7u << 14),(0x7u << 17)>(w2, w2, xpr[3], nb, accA);
    dqpm<(0x7u << 20),(0x7u << 7)> (w2, s2, xpr[4], nb, accB);
    dqpm<(0x7u << 10),(0x7u << 13)>(s2, s2, xpr[5], nb, accA);
    // boundary v10: low2 = w0 bits30-31 (via s0 @14, weight 1), hi = w1 bit0 (weight 4)
    dqpm<(0x3u << 14),(0x1u)>      (s0, w1, xpr[6], nb, accB);
    // boundary v21: lo = w1 bit31 (via s1 @15, weight 1), low2 = w2 bits0-1 (weight 2)
    dqpm<(0x1u << 15),(0x3u)>      (s1, w2, xpr[7], nb, accA);
}

__global__ __launch_bounds__(TPB, 7)
void q3_fused_kernel(const float* __restrict__ x, const unsigned* __restrict__ qw,
                     const float* __restrict__ scales,
                     const float* __restrict__ zeros,
                     const float* __restrict__ bias,
                     float* __restrict__ y) {
    __shared__ __align__(8) float xs[GPB * SLOTS];
    __shared__ float wsum[TPB / 32];
    __shared__ int amLast;

    const int tid = threadIdx.x;
    const int gbase = blockIdx.y * GPB;      // first group of this K-slice
    const int kbase = gbase * 32;            // first in-feature

    // Stage x pairs: slot d of each group holds x[j] * 2^e, where the packed
    // field for that slot is v * 2^b (b = in-word bit position, or b-16 when
    // extracted from w>>16). e = (b<=20) ? -b : 16-b. Exact power-of-two
    // scaling; products in the mainloop round identically to x*v.
    for (int i = tid; i < GPB * SLOTS; i += TPB) {
        const int d = i % SLOTS, g = i / SLOTS;
        int j, b;
        if (d < 10)       { j = d;     b = 3 * d; }
        else if (d < 20)  { j = d + 1; b = 3 * d - 29; }
        else if (d < 30)  { j = d + 2; b = 3 * d - 58; }
        else if (d == 30) { j = 10;    b = 30; }    // v10 low2 via s0@14 -> e=-14
        else if (d == 31) { j = 10;    b = -2; }    // v10 hi bit, weight 4 -> e=+2
        else if (d == 32) { j = 21;    b = 31; }    // v21 bit via s1@15 -> e=-15
        else              { j = 21;    b = -1; }    // v21 low2, weight 2 -> e=+1
        const int e = (b <= 20) ? -b : 16 - b;
        const float sc = __uint_as_float((unsigned)(127 + e) << 23);
        xs[g * SLOTS + d] = x[kbase + g * 32 + j] * sc;
    }
    __syncthreads();

    const int c = blockIdx.x * COLS_PER_BLOCK + tid * COLS_PER_THREAD;
    const uint2* __restrict__ q2 = (const uint2*)qw;
    long base = (long)(gbase * 3) * ROWSTRIDE2 + (c >> 1);

    // packed (f32,f32) accumulators: 2 chains per column
    unsigned long long a0A = 0ull, a0B = 0ull, a1A = 0ull, a1B = 0ull;
    const unsigned long long nb = 0xCB000000CB000000ull;   // (-2^23, -2^23)

    // prologue load (group 0 of slice)
    uint2 cw0 = q2[base];
    uint2 cw1 = q2[base + ROWSTRIDE2];
    uint2 cw2 = q2[base + 2 * ROWSTRIDE2];

#pragma unroll
    for (int g = 0; g < GPB; g++) {
        uint2 nw0, nw1, nw2;
        if (g + 1 < GPB) {                   // prefetch next group while computing
            long nbs = base + (long)(3 * (g + 1)) * ROWSTRIDE2;
            nw0 = q2[nbs];
            nw1 = q2[nbs + ROWSTRIDE2];
            nw2 = q2[nbs + 2 * ROWSTRIDE2];
        }
        const unsigned long long* __restrict__ xp =
            (const unsigned long long*)&xs[g * SLOTS];

        const unsigned s00 = cw0.x >> 16, s01 = cw1.x >> 16, s02 = cw2.x >> 16;
        const unsigned s10 = cw0.y >> 16, s11 = cw1.y >> 16, s12 = cw2.y >> 16;

        // half 1: 9 x-pairs live at a time (low register pressure)
        {
            unsigned long long xpr[9];
#pragma unroll
            for (int t = 0; t < 9; t++) xpr[t] = xp[t];
            unpack_h1(cw0.x, cw1.x, s00, s01, xpr, nb, a0A, a0B);
            unpack_h1(cw0.y, cw1.y, s10, s11, xpr, nb, a1A, a1B);
        }
        // half 2: remaining 8 x-pairs
        {
            unsigned long long xpr[8];
#pragma unroll
            for (int t = 0; t < 8; t++) xpr[t] = xp[9 + t];
            unpack_h2(cw1.x, cw2.x, s00, s01, s02, xpr, nb, a0A, a0B);
            unpack_h2(cw1.y, cw2.y, s10, s11, s12, xpr, nb, a1A, a1B);
        }

        cw0 = nw0; cw1 = nw1; cw2 = nw2;
    }

    // collapse chains + packed lanes (fixed order -> deterministic)
    unsigned long long t0, t1;
    asm("add.rn.f32x2 %0, %1, %2;" : "=l"(t0) : "l"(a0A), "l"(a0B));
    asm("add.rn.f32x2 %0, %1, %2;" : "=l"(t1) : "l"(a1A), "l"(a1B));
    union { unsigned long long u; float2 f; } c0, c1;
    c0.u = t0; c1.u = t1;
    float2 o;
    o.x = c0.f.x + c0.f.y;
    o.y = c1.f.x + c1.f.y;
    *(float2*)&g_partial[blockIdx.y * OUTF + c] = o;

    // ---- last-block-done tail reduction for this column stripe ----
    __threadfence();
    if (tid == 0) {
        int old = atomicAdd(&g_count[blockIdx.x], 1);
        amLast = (old == KS - 1);
    }
    __syncthreads();

    if (amLast) {
        // block-wide sum of x (fixed order -> deterministic, same in every stripe)
        const float4* __restrict__ x4 = (const float4*)x;
        float s = 0.f;
#pragma unroll
        for (int i = 0; i < INF / (4 * TPB); i++) {
            float4 v = x4[tid + TPB * i];
            s += (v.x + v.y) + (v.z + v.w);
        }
#pragma unroll
        for (int o2 = 16; o2 > 0; o2 >>= 1) s += __shfl_down_sync(0xffffffffu, s, o2);
        if ((tid & 31) == 0) wsum[tid >> 5] = s;
        __syncthreads();
        const float sumx = (wsum[0] + wsum[1]) + (wsum[2] + wsum[3]);

        // reduce the 32 split-K partials for this stripe in fixed k-order
        float r0 = 0.f, r1 = 0.f;
#pragma unroll
        for (int k = 0; k < KS; k++) {
            float2 p = *(const float2*)&g_partial[k * OUTF + c];
            r0 += p.x; r1 += p.y;
        }

        float2 sc = *(const float2*)&scales[c];
        float2 zr = *(const float2*)&zeros[c];
        float2 bi = *(const float2*)&bias[c];
        float2 oy;
        oy.x = sc.x * r0 - zr.x * sumx + bi.x;
        oy.y = sc.y * r1 - zr.y * sumx + bi.y;
        *(float2*)&y[c] = oy;

        if (tid == 0) g_count[blockIdx.x] = 0;   // reset for next launch/replay
    }
}

extern "C" void kernel_launch(void* const* d_in, const int* in_sizes, int n_in,
                              void* d_out, int out_size) {
    const float*    x      = (const float*)d_in[0];
    const unsigned* qw     = (const unsigned*)d_in[1];   // int32 bits -> uint32
    const float*    scales = (const float*)d_in[2];
    const float*    zeros  = (const float*)d_in[3];
    const float*    bias   = (const float*)d_in[4];
    float*          y      = (float*)d_out;

    dim3 grid(NCB, KS);
    q3_fused_kernel<<<grid, TPB>>>(x, qw, scales, zeros, bias, y);
}